// round 5
// baseline (speedup 1.0000x reference)
#include <cuda_runtime.h>

#define IMG_SIZE 1280
#define NA 3
#define NC 80
#define BB 16
#define GG 160
#define CP 86              // 6 + NC
#define CC (NA * CP)       // 258
#define PLANE (GG * GG)    // 25600 floats per channel plane

#define NQUADS (BB * NA * PLANE / 4)   // 307200
#define THREADS 512

__device__ __forceinline__ float sigmoidf_(float v) {
    return 1.0f / (1.0f + expf(-v));
}

// One thread handles 4 consecutive gx positions (float4 per channel plane).
// 512-thread blocks: each block touches 8KB contiguous per channel plane
// (vs 4KB at 256 threads) -> half the concurrent DRAM streams chip-wide.
// No min-blocks clause: registers free for load batching (R2 lesson).
__global__ __launch_bounds__(THREADS) void anchor_decode_kernel(
    const float* __restrict__ x,
    const float* __restrict__ anchors,
    float* __restrict__ out)
{
    int tid = blockIdx.x * blockDim.x + threadIdx.x;
    if (tid >= NQUADS) return;

    const int quadsPerRow = GG / 4;           // 40
    int gx4  = (tid % quadsPerRow) * 4;
    int rest = tid / quadsPerRow;
    int gy   = rest % GG;
    int ba   = rest / GG;                     // b*NA + a
    int a    = ba % NA;
    int b    = ba / NA;

    const float* base = x + (size_t)(b * CC + a * CP) * PLANE + gy * GG + gx4;

    #define LD4(cp) (*reinterpret_cast<const float4*>(base + (size_t)(cp) * PLANE))

    // Front-batch the 6 box channels -> 6 independent LDG.128 in flight.
    float4 vx   = LD4(0);
    float4 vy   = LD4(1);
    float4 vw   = LD4(2);
    float4 vh   = LD4(3);
    float4 vyaw = LD4(4);
    float4 vconf= LD4(5);

    // argmax over 80 classes, first-max-wins (ascending order + strict >).
    float bestv[4] = {-3.402823466e+38f, -3.402823466e+38f,
                      -3.402823466e+38f, -3.402823466e+38f};
    float besti[4] = {0.0f, 0.0f, 0.0f, 0.0f};

    // Batches of 8 float4 loads, then 8 compares; unroll 2 -> 16 independent
    // loads visible per scheduled iteration.
    #pragma unroll 2
    for (int cb = 0; cb < NC; cb += 8) {
        float4 v[8];
        #pragma unroll
        for (int j = 0; j < 8; j++) v[j] = LD4(6 + cb + j);
        #pragma unroll
        for (int j = 0; j < 8; j++) {
            float fc = (float)(cb + j);
            if (v[j].x > bestv[0]) { bestv[0] = v[j].x; besti[0] = fc; }
            if (v[j].y > bestv[1]) { bestv[1] = v[j].y; besti[1] = fc; }
            if (v[j].z > bestv[2]) { bestv[2] = v[j].z; besti[2] = fc; }
            if (v[j].w > bestv[3]) { bestv[3] = v[j].w; besti[3] = fc; }
        }
    }
    #undef LD4

    const float stride = (float)IMG_SIZE / (float)GG;  // 8.0
    float aw = __ldg(&anchors[a * 2 + 0]);
    float ah = __ldg(&anchors[a * 2 + 1]);

    float ox[4]  = {vx.x, vx.y, vx.z, vx.w};
    float oy[4]  = {vy.x, vy.y, vy.z, vy.w};
    float ow[4]  = {vw.x, vw.y, vw.z, vw.w};
    float oh[4]  = {vh.x, vh.y, vh.z, vh.w};
    float oyw[4] = {vyaw.x, vyaw.y, vyaw.z, vyaw.w};
    float ocf[4] = {vconf.x, vconf.y, vconf.z, vconf.w};

    float o[28];
    #pragma unroll
    for (int j = 0; j < 4; j++) {
        float sx = sigmoidf_(ox[j]);
        float sy = sigmoidf_(oy[j]);
        o[j * 7 + 0] = floorf((sx + (float)(gx4 + j)) * stride);
        o[j * 7 + 1] = floorf((sy + (float)gy) * stride);
        o[j * 7 + 2] = expf(ow[j]) * aw;
        o[j * 7 + 3] = expf(oh[j]) * ah;
        o[j * 7 + 4] = oyw[j];
        o[j * 7 + 5] = sigmoidf_(ocf[j]);
        o[j * 7 + 6] = besti[j];
    }

    // out offset = pos*7 floats, pos%4==0 -> 112B-aligned: 7 float4 stores.
    float* op = out + ((size_t)ba * PLANE + (size_t)gy * GG + gx4) * 7;
    float4* op4 = reinterpret_cast<float4*>(op);
    #pragma unroll
    for (int k = 0; k < 7; k++) {
        __stcs(&op4[k], make_float4(o[k * 4 + 0], o[k * 4 + 1],
                                    o[k * 4 + 2], o[k * 4 + 3]));
    }
}

extern "C" void kernel_launch(void* const* d_in, const int* in_sizes, int n_in,
                              void* d_out, int out_size) {
    const float* x       = (const float*)d_in[0];
    // d_in[1] = target (unused by reference output)
    const float* anchors = (const float*)d_in[2];
    float* out = (float*)d_out;

    const int blocks = (NQUADS + THREADS - 1) / THREADS;  // 600
    anchor_decode_kernel<<<blocks, THREADS>>>(x, anchors, out);
}

// round 6
// speedup vs baseline: 1.0966x; 1.0966x over previous
#include <cuda_runtime.h>

#define IMG_SIZE 1280
#define NA 3
#define NC 80
#define BB 16
#define GG 160
#define CP 86              // 6 + NC
#define CC (NA * CP)       // 258
#define PLANE (GG * GG)    // 25600 floats per channel plane

#define NQUADS (BB * NA * PLANE / 4)   // 307200
#define THREADS 256

__device__ __forceinline__ float sigmoidf_(float v) {
    return 1.0f / (1.0f + expf(-v));
}

// One thread handles 4 consecutive gx positions (float4 per channel plane).
// __launch_bounds__(256, 4): cap regs at exactly 64 so 4 blocks/SM fit
// (R1's regs=64 -> 32 warps/SM gave the best DRAM%; R3's regs=66 lost a
// whole block). Gentle 2-reg trim, NOT the brutal 32-reg cap that broke R2.
__global__ __launch_bounds__(THREADS, 4) void anchor_decode_kernel(
    const float* __restrict__ x,
    const float* __restrict__ anchors,
    float* __restrict__ out)
{
    int tid = blockIdx.x * blockDim.x + threadIdx.x;
    if (tid >= NQUADS) return;

    const int quadsPerRow = GG / 4;           // 40
    int gx4  = (tid % quadsPerRow) * 4;
    int rest = tid / quadsPerRow;
    int gy   = rest % GG;
    int ba   = rest / GG;                     // b*NA + a
    int a    = ba % NA;
    int b    = ba / NA;

    const float* base = x + (size_t)(b * CC + a * CP) * PLANE + gy * GG + gx4;

    #define LD4(cp) (*reinterpret_cast<const float4*>(base + (size_t)(cp) * PLANE))

    // Front-batch the 6 box channels -> 6 independent LDG.128 in flight.
    float4 vx   = LD4(0);
    float4 vy   = LD4(1);
    float4 vw   = LD4(2);
    float4 vh   = LD4(3);
    float4 vyaw = LD4(4);
    float4 vconf= LD4(5);

    // argmax over 80 classes, first-max-wins (ascending order + strict >).
    float bestv[4] = {-3.402823466e+38f, -3.402823466e+38f,
                      -3.402823466e+38f, -3.402823466e+38f};
    float besti[4] = {0.0f, 0.0f, 0.0f, 0.0f};

    // Batches of 8 float4 loads, then 8 compares; unroll 2 -> 16 independent
    // loads visible per scheduled iteration.
    #pragma unroll 2
    for (int cb = 0; cb < NC; cb += 8) {
        float4 v[8];
        #pragma unroll
        for (int j = 0; j < 8; j++) v[j] = LD4(6 + cb + j);
        #pragma unroll
        for (int j = 0; j < 8; j++) {
            float fc = (float)(cb + j);
            if (v[j].x > bestv[0]) { bestv[0] = v[j].x; besti[0] = fc; }
            if (v[j].y > bestv[1]) { bestv[1] = v[j].y; besti[1] = fc; }
            if (v[j].z > bestv[2]) { bestv[2] = v[j].z; besti[2] = fc; }
            if (v[j].w > bestv[3]) { bestv[3] = v[j].w; besti[3] = fc; }
        }
    }
    #undef LD4

    const float stride = (float)IMG_SIZE / (float)GG;  // 8.0
    float aw = __ldg(&anchors[a * 2 + 0]);
    float ah = __ldg(&anchors[a * 2 + 1]);

    float ox[4]  = {vx.x, vx.y, vx.z, vx.w};
    float oy[4]  = {vy.x, vy.y, vy.z, vy.w};
    float ow[4]  = {vw.x, vw.y, vw.z, vw.w};
    float oh[4]  = {vh.x, vh.y, vh.z, vh.w};
    float oyw[4] = {vyaw.x, vyaw.y, vyaw.z, vyaw.w};
    float ocf[4] = {vconf.x, vconf.y, vconf.z, vconf.w};

    float o[28];
    #pragma unroll
    for (int j = 0; j < 4; j++) {
        float sx = sigmoidf_(ox[j]);
        float sy = sigmoidf_(oy[j]);
        o[j * 7 + 0] = floorf((sx + (float)(gx4 + j)) * stride);
        o[j * 7 + 1] = floorf((sy + (float)gy) * stride);
        o[j * 7 + 2] = expf(ow[j]) * aw;
        o[j * 7 + 3] = expf(oh[j]) * ah;
        o[j * 7 + 4] = oyw[j];
        o[j * 7 + 5] = sigmoidf_(ocf[j]);
        o[j * 7 + 6] = besti[j];
    }

    // out offset = pos*7 floats, pos%4==0 -> 112B-aligned: 7 float4 stores.
    float* op = out + ((size_t)ba * PLANE + (size_t)gy * GG + gx4) * 7;
    float4* op4 = reinterpret_cast<float4*>(op);
    #pragma unroll
    for (int k = 0; k < 7; k++) {
        __stcs(&op4[k], make_float4(o[k * 4 + 0], o[k * 4 + 1],
                                    o[k * 4 + 2], o[k * 4 + 3]));
    }
}

extern "C" void kernel_launch(void* const* d_in, const int* in_sizes, int n_in,
                              void* d_out, int out_size) {
    const float* x       = (const float*)d_in[0];
    // d_in[1] = target (unused by reference output)
    const float* anchors = (const float*)d_in[2];
    float* out = (float*)d_out;

    const int blocks = (NQUADS + THREADS - 1) / THREADS;  // 1200
    anchor_decode_kernel<<<blocks, THREADS>>>(x, anchors, out);
}